// round 3
// baseline (speedup 1.0000x reference)
#include <cuda_runtime.h>
#include <cmath>

#define DIM   64
#define MAXN  50000
#define MAXR  8
#define MAXE  800000

typedef unsigned long long u64;

// ---------------- scratch (static device globals; no allocation) ----------------
__device__ __align__(256) float g_xw[(size_t)MAXN * MAXR * DIM];  // [N,R,64]
__device__ __align__(256) float g_h [(size_t)MAXN * DIM];         // layer-1 output
__device__ float g_qi[MAXN * MAXR];          // qi[n*R+r] = (x[n]W[r]).q
__device__ float g_kj[MAXN * MAXR];          // kj[n*R+r] = (x[n]W[r]).k
__device__ float g_s [MAXN];                 // segment sum of exp (layer 2, for alpha)
__device__ float g_e [MAXE];                 // exp per edge (layer 2, for alpha)
// CSR
__device__ int   g_deg [MAXN];
__device__ int   g_cur [MAXN];
__device__ int   g_off [MAXN];
__device__ int   g_esrcr[MAXE];              // src*R + etype, sorted by dst
__device__ unsigned char g_er[MAXE];         // etype, sorted by dst
__device__ int   g_eorig[MAXE];              // original edge id, sorted by dst

// ---------------- f32x2 packed helpers (sm_103a) ----------------
__device__ __forceinline__ u64 pack2(float lo, float hi) {
    u64 r; asm("mov.b64 %0, {%1, %2};" : "=l"(r) : "f"(lo), "f"(hi)); return r;
}
__device__ __forceinline__ u64 fma2(u64 a, u64 b, u64 c) {
    u64 d; asm("fma.rn.f32x2 %0, %1, %2, %3;" : "=l"(d) : "l"(a), "l"(b), "l"(c)); return d;
}
__device__ __forceinline__ float2 unpack2(u64 v) {
    float2 f; asm("mov.b64 {%0, %1}, %2;" : "=f"(f.x), "=f"(f.y) : "l"(v)); return f;
}

// ---------------- CSR build ----------------
__global__ void k_zero(int N) {
    int i = blockIdx.x * blockDim.x + threadIdx.x;
    if (i < N) { g_deg[i] = 0; g_cur[i] = 0; }
}

__global__ void k_hist(const int* __restrict__ dst, int E) {
    int e = blockIdx.x * blockDim.x + threadIdx.x;
    if (e < E) atomicAdd(&g_deg[dst[e]], 1);
}

// single-block exclusive scan of g_deg -> g_off  (1024 threads)
__global__ void k_scan(int N) {
    __shared__ int wsum[32];
    int tid = threadIdx.x;
    int per = (N + 1023) / 1024;
    int start = tid * per;
    int end = min(start + per, N);
    int local = 0;
    for (int i = start; i < end; i++) local += g_deg[i];
    int lane = tid & 31, w = tid >> 5;
    int v = local;
#pragma unroll
    for (int o = 1; o < 32; o <<= 1) {
        int u = __shfl_up_sync(0xffffffffu, v, o);
        if (lane >= o) v += u;
    }
    if (lane == 31) wsum[w] = v;
    __syncthreads();
    if (w == 0) {
        int s = wsum[lane];
#pragma unroll
        for (int o = 1; o < 32; o <<= 1) {
            int u = __shfl_up_sync(0xffffffffu, s, o);
            if (lane >= o) s += u;
        }
        wsum[lane] = s;
    }
    __syncthreads();
    int excl = v - local + (w > 0 ? wsum[w - 1] : 0);
    int run = excl;
    for (int i = start; i < end; i++) { g_off[i] = run; run += g_deg[i]; }
}

__global__ void k_scatter(const int* __restrict__ src, const int* __restrict__ dst,
                          const int* __restrict__ et, int E, int R) {
    int e = blockIdx.x * blockDim.x + threadIdx.x;
    if (e >= E) return;
    int d = dst[e];
    int pos = g_off[d] + atomicAdd(&g_cur[d], 1);
    int r = et[e];
    g_esrcr[pos] = src[e] * R + r;
    g_er[pos]    = (unsigned char)r;
    g_eorig[pos] = e;
}

// ---------------- GEMM: xw[n,r,:] = x[n,:] @ W[r], fused qi/kj epilogue ----------------
__global__ void k_gemm(const float* __restrict__ X, const float* __restrict__ W,
                       const float* __restrict__ q, const float* __restrict__ k,
                       int N, int R) {
    const int r  = blockIdx.y;
    const int n0 = blockIdx.x * 64;
    __shared__ float Ws[64 * 64];
    __shared__ float Xs[64 * 64];
    __shared__ float qs[64], ks[64];
    const int tid = threadIdx.x;  // 256

    if (tid < 64) { qs[tid] = q[tid]; ks[tid] = k[tid]; }

    const float4* Wg = (const float4*)(W + (size_t)r * 4096);
    float4* Ws4 = (float4*)Ws;
#pragma unroll
    for (int j = 0; j < 4; j++) Ws4[tid + 256 * j] = Wg[tid + 256 * j];

    float4* Xs4 = (float4*)Xs;
#pragma unroll
    for (int j = 0; j < 4; j++) {
        int idx = tid + 256 * j;
        int row = idx >> 4, c4 = idx & 15;
        int n = n0 + row;
        float4 v = make_float4(0.f, 0.f, 0.f, 0.f);
        if (n < N) v = ((const float4*)X)[(size_t)n * 16 + c4];
        Xs4[idx] = v;
    }
    __syncthreads();

    const int tx = tid & 15;
    const int ty = tid >> 4;
    u64 acc2[4][2];
#pragma unroll
    for (int a = 0; a < 4; a++) { acc2[a][0] = pack2(0.f, 0.f); acc2[a][1] = pack2(0.f, 0.f); }

#pragma unroll
    for (int i = 0; i < 64; i++) {
        float4 w = *(const float4*)&Ws[i * 64 + tx * 4];
        u64 w01 = pack2(w.x, w.y);
        u64 w23 = pack2(w.z, w.w);
#pragma unroll
        for (int a = 0; a < 4; a++) {
            float xa = Xs[(ty * 4 + a) * 64 + i];
            u64 xx = pack2(xa, xa);
            acc2[a][0] = fma2(xx, w01, acc2[a][0]);
            acc2[a][1] = fma2(xx, w23, acc2[a][1]);
        }
    }

    // unpack, store xw, fused qi/kj
    float acc[4][4];
#pragma unroll
    for (int a = 0; a < 4; a++) {
        float2 u0 = unpack2(acc2[a][0]);
        float2 u1 = unpack2(acc2[a][1]);
        acc[a][0] = u0.x; acc[a][1] = u0.y; acc[a][2] = u1.x; acc[a][3] = u1.y;
    }

    float pq[4], pk[4];
#pragma unroll
    for (int a = 0; a < 4; a++) {
        pq[a] = acc[a][0] * qs[tx * 4 + 0] + acc[a][1] * qs[tx * 4 + 1]
              + acc[a][2] * qs[tx * 4 + 2] + acc[a][3] * qs[tx * 4 + 3];
        pk[a] = acc[a][0] * ks[tx * 4 + 0] + acc[a][1] * ks[tx * 4 + 1]
              + acc[a][2] * ks[tx * 4 + 2] + acc[a][3] * ks[tx * 4 + 3];
    }
#pragma unroll
    for (int o = 1; o < 16; o <<= 1) {
#pragma unroll
        for (int a = 0; a < 4; a++) {
            pq[a] += __shfl_xor_sync(0xffffffffu, pq[a], o);
            pk[a] += __shfl_xor_sync(0xffffffffu, pk[a], o);
        }
    }

#pragma unroll
    for (int a = 0; a < 4; a++) {
        int n = n0 + ty * 4 + a;
        if (n < N) {
            float4 v = make_float4(acc[a][0], acc[a][1], acc[a][2], acc[a][3]);
            *(float4*)&g_xw[((size_t)n * R + r) * DIM + tx * 4] = v;
            if (tx == 0) {
                g_qi[n * R + r] = pq[a];
                g_kj[n * R + r] = pk[a];
            }
        }
    }
}

// ---------------- fused aggregation: warp per destination node ----------------
// out[d] = relu( (sum_e ev*xw[src_e,r_e]) / (s+eps) + b ),  s = sum_e ev
__global__ void k_agg(float* __restrict__ out, const float* __restrict__ bias,
                      int N, int R, int store_e) {
    int warp_id = (blockIdx.x * blockDim.x + threadIdx.x) >> 5;
    int lane = threadIdx.x & 31;
    if (warp_id >= N) return;
    int d = warp_id;
    int beg = g_off[d];
    int deg = g_deg[d];

    float qiv = (lane < R) ? g_qi[d * R + lane] : 0.f;
    float acc0 = 0.f, acc1 = 0.f, s = 0.f;

    for (int base = 0; base < deg; base += 32) {
        int m = min(32, deg - base);
        int srl = (lane < m) ? g_esrcr[beg + base + lane] : 0;
        int erl = (lane < m) ? (int)g_er[beg + base + lane] : 0;
        float myev = 0.f;
        for (int j = 0; j < m; j++) {
            int sr = __shfl_sync(0xffffffffu, srl, j);
            int rr = __shfl_sync(0xffffffffu, erl, j);
            float l = __shfl_sync(0xffffffffu, qiv, rr) + g_kj[sr];
            l = (l >= 0.f) ? l : 0.2f * l;
            float ev = __expf(l);
            s += ev * (1.f / 32.f) * 0.f;     // (keep s scalar: each lane adds same ev below)
            s += 0.f;
            // all lanes hold the same ev; accumulate message
            float2 v = *(const float2*)&g_xw[(size_t)sr * DIM + lane * 2];
            acc0 += ev * v.x;
            acc1 += ev * v.y;
            if (lane == j) myev = ev;
            if (lane == 0) s += ev;   // placeholder replaced below
        }
        if (store_e && lane < m) g_e[g_eorig[beg + base + lane]] = myev;
    }
    // s was accumulated only in lane 0; broadcast
    s = __shfl_sync(0xffffffffu, s, 0);

    if (lane == 0) g_s[d] = s;
    float inv = 1.f / (s + 1e-16f);
    int c = lane * 2;
    float2 o;
    o.x = fmaxf(acc0 * inv + bias[c],     0.f);
    o.y = fmaxf(acc1 * inv + bias[c + 1], 0.f);
    *(float2*)&out[(size_t)d * DIM + c] = o;
}

// alpha[e] = e[e] / (s[dst[e]] + eps)
__global__ void k_alpha(const int* __restrict__ dst, float* __restrict__ alpha, int E) {
    int e = blockIdx.x * blockDim.x + threadIdx.x;
    if (e >= E) return;
    alpha[e] = g_e[e] / (g_s[dst[e]] + 1e-16f);
}

__global__ void k_copy_edges(const int* __restrict__ ei, float* __restrict__ out, int n2e) {
    int i = blockIdx.x * blockDim.x + threadIdx.x;
    if (i < n2e) out[i] = (float)ei[i];
}

// ---------------- host orchestration ----------------
extern "C" void kernel_launch(void* const* d_in, const int* in_sizes, int n_in,
                              void* d_out, int out_size) {
    const float* x   = (const float*)d_in[0];
    const int*   ei  = (const int*)d_in[1];   // [2,E]: row0=src, row1=dst
    const int*   et  = (const int*)d_in[2];
    const float* W1  = (const float*)d_in[3];
    const float* q1  = (const float*)d_in[4];
    const float* k1  = (const float*)d_in[5];
    const float* b1  = (const float*)d_in[6];
    const float* W2  = (const float*)d_in[7];
    const float* q2  = (const float*)d_in[8];
    const float* k2  = (const float*)d_in[9];
    const float* b2  = (const float*)d_in[10];

    const int N = in_sizes[0] / DIM;
    const int E = in_sizes[2];
    const int R = in_sizes[3] / (DIM * DIM);

    const int* src = ei;
    const int* dst = ei + E;

    float* h1;
    cudaGetSymbolAddress((void**)&h1, g_h);

    float* outf  = (float*)d_out;
    float* h2    = outf;                         // [N*64]
    float* eidxo = outf + (size_t)N * DIM;       // [2E]
    float* alpo  = eidxo + 2 * (size_t)E;        // [E]

    dim3 gg((N + 63) / 64, R);
    const int aggBlocks = (N + 7) / 8;           // 8 warps per 256-thr block

    // idx 0..2: CSR prep
    k_zero<<<(N + 255) / 256, 256>>>(N);
    k_hist<<<(E + 255) / 256, 256>>>(dst, E);
    k_scan<<<1, 1024>>>(N);
    // idx 3: layer-1 GEMM (profiled slot)
    k_gemm<<<gg, 256>>>(x, W1, q1, k1, N, R);
    // idx 4: CSR scatter
    k_scatter<<<(E + 255) / 256, 256>>>(src, dst, et, E, R);
    // idx 5: layer-1 aggregation -> h1
    k_agg<<<aggBlocks, 256>>>(h1, b1, N, R, 0);
    // idx 6,7: layer 2
    k_gemm<<<gg, 256>>>(h1, W2, q2, k2, N, R);
    k_agg<<<aggBlocks, 256>>>(h2, b2, N, R, 1);
    // idx 8,9: outputs
    k_alpha<<<(E + 255) / 256, 256>>>(dst, alpo, E);
    k_copy_edges<<<(2 * E + 255) / 256, 256>>>(ei, eidxo, 2 * E);
}

// round 4
// speedup vs baseline: 1.1306x; 1.1306x over previous
#include <cuda_runtime.h>
#include <cmath>

#define DIM   64
#define MAXN  50000
#define MAXR  8
#define MAXE  800000

typedef unsigned long long u64;

// ---------------- scratch (static device globals; no allocation) ----------------
__device__ __align__(256) float g_xw[(size_t)MAXN * MAXR * DIM];  // [N,R,64]
__device__ __align__(256) float g_h [(size_t)MAXN * DIM];         // layer-1 output
__device__ float g_qi[MAXN * MAXR];          // qi[n*R+r] = (x[n]W[r]).q
__device__ float g_kj[MAXN * MAXR];          // kj[n*R+r] = (x[n]W[r]).k
__device__ float g_s [MAXN];                 // segment sum of exp (layer 2, for alpha)
__device__ float g_e [MAXE];                 // exp per edge (layer 2, for alpha)
// CSR (built once, reused by both layers)
__device__ int   g_deg [MAXN];
__device__ int   g_cur [MAXN];
__device__ int   g_off [MAXN];
__device__ int   g_esrcr[MAXE];              // src*R + etype, sorted by dst (== xw row, kj idx)
__device__ unsigned char g_er[MAXE];         // etype, sorted by dst
__device__ int   g_eorig[MAXE];              // original edge id, sorted by dst

// ---------------- f32x2 packed helpers (sm_103a) ----------------
__device__ __forceinline__ u64 pack2(float lo, float hi) {
    u64 r; asm("mov.b64 %0, {%1, %2};" : "=l"(r) : "f"(lo), "f"(hi)); return r;
}
__device__ __forceinline__ u64 fma2(u64 a, u64 b, u64 c) {
    u64 d; asm("fma.rn.f32x2 %0, %1, %2, %3;" : "=l"(d) : "l"(a), "l"(b), "l"(c)); return d;
}
__device__ __forceinline__ float2 unpack2(u64 v) {
    float2 f; asm("mov.b64 {%0, %1}, %2;" : "=f"(f.x), "=f"(f.y) : "l"(v)); return f;
}

// ---------------- CSR build ----------------
__global__ void k_zero(int N) {
    int i = blockIdx.x * blockDim.x + threadIdx.x;
    if (i < N) { g_deg[i] = 0; g_cur[i] = 0; }
}

__global__ void k_hist(const int* __restrict__ dst, int E) {
    int e = blockIdx.x * blockDim.x + threadIdx.x;
    if (e < E) atomicAdd(&g_deg[dst[e]], 1);
}

// single-block exclusive scan of g_deg -> g_off  (1024 threads)
__global__ void k_scan(int N) {
    __shared__ int wsum[32];
    int tid = threadIdx.x;
    int per = (N + 1023) / 1024;
    int start = tid * per;
    int end = min(start + per, N);
    int local = 0;
    for (int i = start; i < end; i++) local += g_deg[i];
    int lane = tid & 31, w = tid >> 5;
    int v = local;
#pragma unroll
    for (int o = 1; o < 32; o <<= 1) {
        int u = __shfl_up_sync(0xffffffffu, v, o);
        if (lane >= o) v += u;
    }
    if (lane == 31) wsum[w] = v;
    __syncthreads();
    if (w == 0) {
        int s = wsum[lane];
#pragma unroll
        for (int o = 1; o < 32; o <<= 1) {
            int u = __shfl_up_sync(0xffffffffu, s, o);
            if (lane >= o) s += u;
        }
        wsum[lane] = s;
    }
    __syncthreads();
    int excl = v - local + (w > 0 ? wsum[w - 1] : 0);
    int run = excl;
    for (int i = start; i < end; i++) { g_off[i] = run; run += g_deg[i]; }
}

__global__ void k_scatter(const int* __restrict__ src, const int* __restrict__ dst,
                          const int* __restrict__ et, int E, int R) {
    int e = blockIdx.x * blockDim.x + threadIdx.x;
    if (e >= E) return;
    int d = dst[e];
    int pos = g_off[d] + atomicAdd(&g_cur[d], 1);
    int r = et[e];
    g_esrcr[pos] = src[e] * R + r;
    g_er[pos]    = (unsigned char)r;
    g_eorig[pos] = e;
}

// ---------------- GEMM: xw[n,r,:] = x[n,:] @ W[r], fused qi/kj epilogue ----------------
// k-chunked float4 LDS reads (12 wavefronts / 4 k-iters per warp) + f32x2 FMA.
__global__ void __launch_bounds__(256) k_gemm(
        const float* __restrict__ X, const float* __restrict__ W,
        const float* __restrict__ q, const float* __restrict__ k,
        int N, int R) {
    const int r  = blockIdx.y;
    const int n0 = blockIdx.x * 64;
    __shared__ float Ws[64 * 64];
    __shared__ float Xs[64 * 64];
    __shared__ float qs[64], ks[64];
    const int tid = threadIdx.x;  // 256

    if (tid < 64) { qs[tid] = q[tid]; ks[tid] = k[tid]; }

    const float4* Wg = (const float4*)(W + (size_t)r * 4096);
    float4* Ws4 = (float4*)Ws;
#pragma unroll
    for (int j = 0; j < 4; j++) Ws4[tid + 256 * j] = Wg[tid + 256 * j];

    float4* Xs4 = (float4*)Xs;
#pragma unroll
    for (int j = 0; j < 4; j++) {
        int idx = tid + 256 * j;
        int row = idx >> 4, c4 = idx & 15;
        int n = n0 + row;
        float4 v = make_float4(0.f, 0.f, 0.f, 0.f);
        if (n < N) v = ((const float4*)X)[(size_t)n * 16 + c4];
        Xs4[idx] = v;
    }
    __syncthreads();

    const int tx = tid & 15;
    const int ty = tid >> 4;
    u64 acc2[4][2];
#pragma unroll
    for (int a = 0; a < 4; a++) { acc2[a][0] = pack2(0.f, 0.f); acc2[a][1] = pack2(0.f, 0.f); }

#pragma unroll
    for (int kk = 0; kk < 64; kk += 4) {
        u64 wlo[4], whi[4];
#pragma unroll
        for (int j = 0; j < 4; j++) {
            float4 w = *(const float4*)&Ws[(kk + j) * 64 + tx * 4];
            wlo[j] = pack2(w.x, w.y);
            whi[j] = pack2(w.z, w.w);
        }
#pragma unroll
        for (int a = 0; a < 4; a++) {
            float4 xa = *(const float4*)&Xs[(ty * 4 + a) * 64 + kk];
            u64 x0 = pack2(xa.x, xa.x);
            u64 x1 = pack2(xa.y, xa.y);
            u64 x2 = pack2(xa.z, xa.z);
            u64 x3 = pack2(xa.w, xa.w);
            acc2[a][0] = fma2(x0, wlo[0], acc2[a][0]);
            acc2[a][1] = fma2(x0, whi[0], acc2[a][1]);
            acc2[a][0] = fma2(x1, wlo[1], acc2[a][0]);
            acc2[a][1] = fma2(x1, whi[1], acc2[a][1]);
            acc2[a][0] = fma2(x2, wlo[2], acc2[a][0]);
            acc2[a][1] = fma2(x2, whi[2], acc2[a][1]);
            acc2[a][0] = fma2(x3, wlo[3], acc2[a][0]);
            acc2[a][1] = fma2(x3, whi[3], acc2[a][1]);
        }
    }

    float acc[4][4];
#pragma unroll
    for (int a = 0; a < 4; a++) {
        float2 u0 = unpack2(acc2[a][0]);
        float2 u1 = unpack2(acc2[a][1]);
        acc[a][0] = u0.x; acc[a][1] = u0.y; acc[a][2] = u1.x; acc[a][3] = u1.y;
    }

    float pq[4], pk[4];
#pragma unroll
    for (int a = 0; a < 4; a++) {
        pq[a] = acc[a][0] * qs[tx * 4 + 0] + acc[a][1] * qs[tx * 4 + 1]
              + acc[a][2] * qs[tx * 4 + 2] + acc[a][3] * qs[tx * 4 + 3];
        pk[a] = acc[a][0] * ks[tx * 4 + 0] + acc[a][1] * ks[tx * 4 + 1]
              + acc[a][2] * ks[tx * 4 + 2] + acc[a][3] * ks[tx * 4 + 3];
    }
#pragma unroll
    for (int o = 1; o < 16; o <<= 1) {
#pragma unroll
        for (int a = 0; a < 4; a++) {
            pq[a] += __shfl_xor_sync(0xffffffffu, pq[a], o);
            pk[a] += __shfl_xor_sync(0xffffffffu, pk[a], o);
        }
    }

#pragma unroll
    for (int a = 0; a < 4; a++) {
        int n = n0 + ty * 4 + a;
        if (n < N) {
            float4 v = make_float4(acc[a][0], acc[a][1], acc[a][2], acc[a][3]);
            *(float4*)&g_xw[((size_t)n * R + r) * DIM + tx * 4] = v;
            if (tx == 0) {
                g_qi[n * R + r] = pq[a];
                g_kj[n * R + r] = pk[a];
            }
        }
    }
}

// ---------------- fused aggregation: warp per destination node ----------------
// out[d] = relu( (sum_e ev*xw[esrcr_e]) / (s+eps) + b ),  s = sum_e ev
// All lanes compute ev redundantly from uniform (broadcast) loads; unroll-4 for MLP.
__global__ void k_agg(float* __restrict__ out, const float* __restrict__ bias,
                      int N, int R, int store_e) {
    int d = (blockIdx.x * blockDim.x + threadIdx.x) >> 5;
    int lane = threadIdx.x & 31;
    if (d >= N) return;
    int beg = g_off[d];
    int deg = g_deg[d];
    const float* qrow = g_qi + d * R;

    float acc0 = 0.f, acc1 = 0.f, s = 0.f;

    for (int base = 0; base < deg; base += 4) {
        int vv[4], rr[4];
#pragma unroll
        for (int j = 0; j < 4; j++) {
            int idx = beg + min(base + j, deg - 1);
            vv[j] = g_esrcr[idx];
            rr[j] = (int)g_er[idx];
        }
        float ev[4];
#pragma unroll
        for (int j = 0; j < 4; j++) {
            float l = qrow[rr[j]] + g_kj[vv[j]];
            l = (l >= 0.f) ? l : 0.2f * l;
            float e = __expf(l);
            ev[j] = (base + j < deg) ? e : 0.f;
            s += ev[j];
        }
#pragma unroll
        for (int j = 0; j < 4; j++) {
            float2 xv = *(const float2*)&g_xw[(size_t)vv[j] * DIM + lane * 2];
            acc0 += ev[j] * xv.x;
            acc1 += ev[j] * xv.y;
        }
        if (store_e && lane == 0) {
#pragma unroll
            for (int j = 0; j < 4; j++)
                if (base + j < deg) g_e[g_eorig[beg + base + j]] = ev[j];
        }
    }

    if (lane == 0) g_s[d] = s;
    float inv = 1.f / (s + 1e-16f);
    int c = lane * 2;
    float2 o;
    o.x = fmaxf(acc0 * inv + bias[c],     0.f);
    o.y = fmaxf(acc1 * inv + bias[c + 1], 0.f);
    *(float2*)&out[(size_t)d * DIM + c] = o;
}

// alpha[e] = e[e] / (s[dst[e]] + eps)
__global__ void k_alpha(const int* __restrict__ dst, float* __restrict__ alpha, int E) {
    int e = blockIdx.x * blockDim.x + threadIdx.x;
    if (e >= E) return;
    alpha[e] = g_e[e] / (g_s[dst[e]] + 1e-16f);
}

__global__ void k_copy_edges(const int* __restrict__ ei, float* __restrict__ out, int n2e) {
    int i = blockIdx.x * blockDim.x + threadIdx.x;
    if (i < n2e) out[i] = (float)ei[i];
}

// ---------------- host orchestration ----------------
extern "C" void kernel_launch(void* const* d_in, const int* in_sizes, int n_in,
                              void* d_out, int out_size) {
    const float* x   = (const float*)d_in[0];
    const int*   ei  = (const int*)d_in[1];   // [2,E]: row0=src, row1=dst
    const int*   et  = (const int*)d_in[2];
    const float* W1  = (const float*)d_in[3];
    const float* q1  = (const float*)d_in[4];
    const float* k1  = (const float*)d_in[5];
    const float* b1  = (const float*)d_in[6];
    const float* W2  = (const float*)d_in[7];
    const float* q2  = (const float*)d_in[8];
    const float* k2  = (const float*)d_in[9];
    const float* b2  = (const float*)d_in[10];

    const int N = in_sizes[0] / DIM;
    const int E = in_sizes[2];
    const int R = in_sizes[3] / (DIM * DIM);

    const int* src = ei;
    const int* dst = ei + E;

    float* h1;
    cudaGetSymbolAddress((void**)&h1, g_h);

    float* outf  = (float*)d_out;
    float* h2    = outf;                         // [N*64]
    float* eidxo = outf + (size_t)N * DIM;       // [2E]
    float* alpo  = eidxo + 2 * (size_t)E;        // [E]

    dim3 gg((N + 63) / 64, R);
    const int aggBlocks = (N + 7) / 8;           // 8 warps per 256-thr block

    // idx 0..2: CSR prep
    k_zero<<<(N + 255) / 256, 256>>>(N);
    k_hist<<<(E + 255) / 256, 256>>>(dst, E);
    k_scan<<<1, 1024>>>(N);
    // idx 3: layer-1 GEMM (ncu profiled slot — verify LDS fix)
    k_gemm<<<gg, 256>>>(x, W1, q1, k1, N, R);
    // idx 4: CSR scatter
    k_scatter<<<(E + 255) / 256, 256>>>(src, dst, et, E, R);
    // idx 5: layer-1 aggregation -> h1
    k_agg<<<aggBlocks, 256>>>(h1, b1, N, R, 0);
    // idx 6,7: layer 2
    k_gemm<<<gg, 256>>>(h1, W2, q2, k2, N, R);
    k_agg<<<aggBlocks, 256>>>(h2, b2, N, R, 1);
    // idx 8,9: outputs
    k_alpha<<<(E + 255) / 256, 256>>>(dst, alpo, E);
    k_copy_edges<<<(2 * E + 255) / 256, 256>>>(ei, eidxo, 2 * E);
}

// round 6
// speedup vs baseline: 1.3213x; 1.1686x over previous
#include <cuda_runtime.h>
#include <cuda_bf16.h>
#include <cstdint>
#include <cmath>

#define DIM    64
#define MAXN   50000
#define MAXR   8
#define MAXE   800000
#define TILE_M 128
#define LDA    72          // padded smem row length (bf16 elems)

typedef uint32_t u32;

// ---------------- scratch (static device globals; no allocation) ----------------
__device__ __align__(256) float g_xw[(size_t)MAXR * MAXN * DIM];  // [R][N][64]
__device__ __align__(256) float g_h [(size_t)MAXN * DIM];
__device__ float g_qi[MAXN * MAXR];          // [n][r]
__device__ float g_kj[(size_t)MAXR * MAXN];  // [r][n]
__device__ float g_s [MAXN];
__device__ float g_e [MAXE];
// CSR
__device__ int   g_deg [MAXN];
__device__ int   g_cur [MAXN];
__device__ int   g_off [MAXN];
__device__ int   g_esrcr[MAXE];              // r*N + src  (== xw/kj row), sorted by dst
__device__ unsigned char g_er[MAXE];
__device__ int   g_eorig[MAXE];
// bf16 splits
__device__ __nv_bfloat16 g_xhi[(size_t)MAXN * DIM];
__device__ __nv_bfloat16 g_xlo[(size_t)MAXN * DIM];
__device__ __nv_bfloat16 g_whi[MAXR * DIM * DIM];   // W^T: [r][o][k]
__device__ __nv_bfloat16 g_wlo[MAXR * DIM * DIM];

// ---------------- bf16 split prep ----------------
__global__ void k_split(const float* __restrict__ src, __nv_bfloat16* __restrict__ hi,
                        __nv_bfloat16* __restrict__ lo, int n) {
    int i = blockIdx.x * blockDim.x + threadIdx.x;
    if (i >= n) return;
    float v = src[i];
    __nv_bfloat16 h = __float2bfloat16(v);
    hi[i] = h;
    lo[i] = __float2bfloat16(v - __bfloat162float(h));
}

// W [R,64(k),64(o)] -> Wt [R,64(o),64(k)] split hi/lo
__global__ void k_splitW(const float* __restrict__ W, __nv_bfloat16* __restrict__ whi,
                         __nv_bfloat16* __restrict__ wlo, int R) {
    int i = blockIdx.x * blockDim.x + threadIdx.x;
    if (i >= R * DIM * DIM) return;
    int r = i >> 12, rem = i & 4095, o = rem >> 6, kk = rem & 63;
    float v = W[(r << 12) + kk * 64 + o];
    __nv_bfloat16 h = __float2bfloat16(v);
    whi[i] = h;
    wlo[i] = __float2bfloat16(v - __bfloat162float(h));
}

// ---------------- MMA helper ----------------
__device__ __forceinline__ void mma16816(float* d, const u32* a, u32 b0, u32 b1) {
    asm volatile(
        "mma.sync.aligned.m16n8k16.row.col.f32.bf16.bf16.f32 "
        "{%0,%1,%2,%3}, {%4,%5,%6,%7}, {%8,%9}, {%0,%1,%2,%3};"
        : "+f"(d[0]), "+f"(d[1]), "+f"(d[2]), "+f"(d[3])
        : "r"(a[0]), "r"(a[1]), "r"(a[2]), "r"(a[3]), "r"(b0), "r"(b1));
}

// SMEM layout (bytes)
#define SM_AHI  0
#define SM_ALO  (SM_AHI + TILE_M * LDA * 2)     // 18432
#define SM_BHI  (SM_ALO + TILE_M * LDA * 2)     // 36864
#define SM_BLO  (SM_BHI + 64 * LDA * 2)         // 46080
#define SM_Q    (SM_BLO + 64 * LDA * 2)         // 55296
#define SM_K    (SM_Q + 256)
#define SM_TOT  (SM_K + 256)                    // 55808

// ---------------- tensor GEMM: xw[r][n][:] = X[n] @ W[r] ----------------
// One block = 128-node tile (8 warps x 16 rows), loops over all R relations.
// bf16 split: XhiWhi + XloWhi + XhiWlo, fp32 accumulate. Fused qi/kj epilogue.
__global__ void __launch_bounds__(256) k_gemm_mma(
        const __nv_bfloat16* __restrict__ xhi, const __nv_bfloat16* __restrict__ xlo,
        const __nv_bfloat16* __restrict__ whi, const __nv_bfloat16* __restrict__ wlo,
        const float* __restrict__ qv, const float* __restrict__ kv, int N, int R) {
    extern __shared__ char smem[];
    __nv_bfloat16* Ahi = (__nv_bfloat16*)(smem + SM_AHI);
    __nv_bfloat16* Alo = (__nv_bfloat16*)(smem + SM_ALO);
    __nv_bfloat16* Bhi = (__nv_bfloat16*)(smem + SM_BHI);
    __nv_bfloat16* Blo = (__nv_bfloat16*)(smem + SM_BLO);
    float* sQ = (float*)(smem + SM_Q);
    float* sK = (float*)(smem + SM_K);

    const int tid = threadIdx.x;
    const int w   = tid >> 5;
    const int lane = tid & 31;
    const int g   = lane >> 2;     // 0..7
    const int tig = lane & 3;      // 0..3
    const int n0  = blockIdx.x * TILE_M;

    if (tid < 64) { sQ[tid] = qv[tid]; sK[tid] = kv[tid]; }

    // stage A tiles (hi, lo): 128 rows x 64 bf16, padded to LDA
    for (int i = tid; i < TILE_M * 8; i += 256) {
        int row = i >> 3, c8 = i & 7;           // c8: 8-bf16 (16B) chunk
        int n = n0 + row;
        uint4 vh = make_uint4(0, 0, 0, 0), vl = vh;
        if (n < N) {
            vh = ((const uint4*)xhi)[(size_t)n * 8 + c8];
            vl = ((const uint4*)xlo)[(size_t)n * 8 + c8];
        }
        *(uint4*)&Ahi[row * LDA + c8 * 8] = vh;
        *(uint4*)&Alo[row * LDA + c8 * 8] = vl;
    }
    __syncthreads();

    // A fragments: loaded ONCE, reused across all relations.
    // [kstep][reg]: reg0=(g,kb+2tig) reg1=(g+8,..) reg2=(g,kb+2tig+8) reg3=(g+8,..+8)
    const int wr = w * 16;
    u32 ahi[4][4], alo[4][4];
#pragma unroll
    for (int ks = 0; ks < 4; ks++) {
        int kb = ks * 16;
        ahi[ks][0] = *(const u32*)&Ahi[(wr + g) * LDA + kb + 2 * tig];
        ahi[ks][1] = *(const u32*)&Ahi[(wr + g + 8) * LDA + kb + 2 * tig];
        ahi[ks][2] = *(const u32*)&Ahi[(wr + g) * LDA + kb + 2 * tig + 8];
        ahi[ks][3] = *(const u32*)&Ahi[(wr + g + 8) * LDA + kb + 2 * tig + 8];
        alo[ks][0] = *(const u32*)&Alo[(wr + g) * LDA + kb + 2 * tig];
        alo[ks][1] = *(const u32*)&Alo[(wr + g + 8) * LDA + kb + 2 * tig];
        alo[ks][2] = *(const u32*)&Alo[(wr + g) * LDA + kb + 2 * tig + 8];
        alo[ks][3] = *(const u32*)&Alo[(wr + g + 8) * LDA + kb + 2 * tig + 8];
    }

    const int nA = n0 + wr + g;        // row for d0,d1
    const int nB = nA + 8;             // row for d2,d3

    for (int r = 0; r < R; r++) {
        // stage B = Wt[r] (hi, lo): 64 rows (o) x 64 (k)
        for (int i = tid; i < 64 * 8; i += 256) {
            int row = i >> 3, c8 = i & 7;
            uint4 vh = ((const uint4*)whi)[(size_t)r * 512 + i];
            uint4 vl = ((const uint4*)wlo)[(size_t)r * 512 + i];
            *(uint4*)&Bhi[row * LDA + c8 * 8] = vh;
            *(uint4*)&Blo[row * LDA + c8 * 8] = vl;
        }
        __syncthreads();

        float d[8][4];
#pragma unroll
        for (int nt = 0; nt < 8; nt++)
#pragma unroll
            for (int j = 0; j < 4; j++) d[nt][j] = 0.f;

#pragma unroll
        for (int ks = 0; ks < 4; ks++) {
            int kb = ks * 16;
#pragma unroll
            for (int nt = 0; nt < 8; nt++) {
                int orow = nt * 8 + g;
                u32 b0h = *(const u32*)&Bhi[orow * LDA + kb + 2 * tig];
                u32 b1h = *(const u32*)&Bhi[orow * LDA + kb + 2 * tig + 8];
                mma16816(d[nt], ahi[ks], b0h, b1h);
                mma16816(d[nt], alo[ks], b0h, b1h);
                u32 b0l = *(const u32*)&Blo[orow * LDA + kb + 2 * tig];
                u32 b1l = *(const u32*)&Blo[orow * LDA + kb + 2 * tig + 8];
                mma16816(d[nt], ahi[ks], b0l, b1l);
            }
        }

        // epilogue: store xw rows + fused qi/kj
        float pqA = 0.f, pkA = 0.f, pqB = 0.f, pkB = 0.f;
        float* baseA = g_xw + ((size_t)r * N + nA) * DIM;
        float* baseB = g_xw + ((size_t)r * N + nB) * DIM;
#pragma unroll
        for (int nt = 0; nt < 8; nt++) {
            int c = nt * 8 + 2 * tig;
            float q0 = sQ[c], q1 = sQ[c + 1], k0 = sK[c], k1 = sK[c + 1];
            pqA += d[nt][0] * q0 + d[nt][1] * q1;
            pkA += d[nt][0] * k0 + d[nt][1] * k1;
            pqB += d[nt][2] * q0 + d[nt][3] * q1;
            pkB += d[nt][2] * k0 + d[nt][3] * k1;
            if (nA < N) *(float2*)(baseA + c) = make_float2(d[nt][0], d[nt][1]);
            if (nB < N) *(float2*)(baseB + c) = make_float2(d[nt][2], d[nt][3]);
        }
        pqA += __shfl_xor_sync(0xffffffffu, pqA, 1);
        pqA += __shfl_xor_sync(0xffffffffu, pqA, 2);
        pkA += __shfl_xor_sync(0xffffffffu, pkA, 1);
        pkA += __shfl_xor_sync(0xffffffffu, pkA, 2);
        pqB += __shfl_xor_sync(0xffffffffu, pqB, 1);
        pqB += __shfl_xor_sync(0xffffffffu, pqB, 2);
        pkB += __shfl_xor_sync(0xffffffffu, pkB, 1);
        pkB += __shfl_xor_sync(0xffffffffu, pkB, 2);
        if (tig == 0) {
            if (nA < N) { g_qi[nA * R + r] = pqA; g_kj[(size_t)r * N + nA] = pkA; }
            if (nB < N) { g_qi[nB * R + r] = pqB; g_kj[(size_t)r * N + nB] = pkB; }
        }
        __syncthreads();   // B tiles reused next relation
    }
}

// ---------------- CSR build ----------------
__global__ void k_zero(int N) {
    int i = blockIdx.x * blockDim.x + threadIdx.x;
    if (i < N) { g_deg[i] = 0; g_cur[i] = 0; }
}
__global__ void k_hist(const int* __restrict__ dst, int E) {
    int e = blockIdx.x * blockDim.x + threadIdx.x;
    if (e < E) atomicAdd(&g_deg[dst[e]], 1);
}
__global__ void k_scan(int N) {
    __shared__ int wsum[32];
    int tid = threadIdx.x;
    int per = (N + 1023) / 1024;
    int start = tid * per;
    int end = min(start + per, N);
    int local = 0;
    for (int i = start; i < end; i++) local += g_deg[i];
    int lane = tid & 31, w = tid >> 5;
    int v = local;
#pragma unroll
    for (int o = 1; o < 32; o <<= 1) {
        int u = __shfl_up_sync(0xffffffffu, v, o);
        if (lane >= o) v += u;
    }
    if (lane == 31) wsum[w] = v;
    __syncthreads();
    if (w == 0) {
        int s = wsum[lane];
#pragma unroll
        for (int o = 1; o < 32; o <<= 1) {
            int u = __shfl_up_sync(0xffffffffu, s, o);
            if (lane >= o) s += u;
        }
        wsum[lane] = s;
    }
    __syncthreads();
    int excl = v - local + (w > 0 ? wsum[w - 1] : 0);
    int run = excl;
    for (int i = start; i < end; i++) { g_off[i] = run; run += g_deg[i]; }
}
__global__ void k_scatter(const int* __restrict__ src, const int* __restrict__ dst,
                          const int* __restrict__ et, int E, int N) {
    int e = blockIdx.x * blockDim.x + threadIdx.x;
    if (e >= E) return;
    int d = dst[e];
    int pos = g_off[d] + atomicAdd(&g_cur[d], 1);
    int r = et[e];
    g_esrcr[pos] = r * N + src[e];
    g_er[pos]    = (unsigned char)r;
    g_eorig[pos] = e;
}

// ---------------- fused aggregation: warp per destination node ----------------
__global__ void k_agg(float* __restrict__ out, const float* __restrict__ bias,
                      int N, int R, int store_e) {
    int d = (blockIdx.x * blockDim.x + threadIdx.x) >> 5;
    int lane = threadIdx.x & 31;
    if (d >= N) return;
    int beg = g_off[d];
    int deg = g_deg[d];
    const float* qrow = g_qi + d * R;

    float acc0 = 0.f, acc1 = 0.f, s = 0.f;

    for (int base = 0; base < deg; base += 4) {
        int vv[4], rr[4];
#pragma unroll
        for (int j = 0; j < 4; j++) {
            int idx = beg + min(base + j, deg - 1);
            vv[j] = g_esrcr[idx];
            rr[j] = (int)g_er[idx];
        }
        float ev[4];
#pragma unroll
        for (int j = 0; j < 4; j++) {
            float l = qrow[rr[j]] + g_kj[vv[j]];
            l = (l >= 0.f) ? l : 0.2f * l;
            float e = __expf(l);
            ev[j] = (base + j < deg) ? e : 0.f;
            s += ev[j];
        }
#pragma unroll
        for (int j = 0; j < 4; j++) {
            float2 xv = *(const float2*)&g_xw[(size_t)vv[j] * DIM + lane * 2];
            acc0 += ev[j] * xv.x;
            acc1 += ev[j] * xv.y;
        }
        if (store_e && lane == 0) {
#pragma unroll
            for (int j = 0; j < 4; j++)
                if (base + j < deg) g_e[g_eorig[beg + base + j]] = ev[j];
        }
    }

    if (lane == 0) g_s[d] = s;
    float inv = 1.f / (s + 1e-16f);
    int c = lane * 2;
    float2 o;
    o.x = fmaxf(acc0 * inv + bias[c],     0.f);
    o.y = fmaxf(acc1 * inv + bias[c + 1], 0.f);
    *(float2*)&out[(size_t)d * DIM + c] = o;
}

__global__ void k_alpha(const int* __restrict__ dst, float* __restrict__ alpha, int E) {
    int e = blockIdx.x * blockDim.x + threadIdx.x;
    if (e >= E) return;
    alpha[e] = g_e[e] / (g_s[dst[e]] + 1e-16f);
}
__global__ void k_copy_edges(const int* __restrict__ ei, float* __restrict__ out, int n2e) {
    int i = blockIdx.x * blockDim.x + threadIdx.x;
    if (i < n2e) out[i] = (float)ei[i];
}

// ---------------- host orchestration ----------------
extern "C" void kernel_launch(void* const* d_in, const int* in_sizes, int n_in,
                              void* d_out, int out_size) {
    const float* x   = (const float*)d_in[0];
    const int*   ei  = (const int*)d_in[1];
    const int*   et  = (const int*)d_in[2];
    const float* W1  = (const float*)d_in[3];
    const float* q1  = (const float*)d_in[4];
    const float* k1  = (const float*)d_in[5];
    const float* b1  = (const float*)d_in[6];
    const float* W2  = (const float*)d_in[7];
    const float* q2  = (const float*)d_in[8];
    const float* k2  = (const float*)d_in[9];
    const float* b2  = (const float*)d_in[10];

    const int N = in_sizes[0] / DIM;
    const int E = in_sizes[2];
    const int R = in_sizes[3] / (DIM * DIM);

    const int* src = ei;
    const int* dst = ei + E;

    cudaFuncSetAttribute(k_gemm_mma, cudaFuncAttributeMaxDynamicSharedMemorySize, SM_TOT);

    float* h1;  cudaGetSymbolAddress((void**)&h1, g_h);
    __nv_bfloat16 *xhi, *xlo, *whi, *wlo;
    cudaGetSymbolAddress((void**)&xhi, g_xhi);
    cudaGetSymbolAddress((void**)&xlo, g_xlo);
    cudaGetSymbolAddress((void**)&whi, g_whi);
    cudaGetSymbolAddress((void**)&wlo, g_wlo);

    float* outf  = (float*)d_out;
    float* h2    = outf;
    float* eidxo = outf + (size_t)N * DIM;
    float* alpo  = eidxo + 2 * (size_t)E;

    const int gemmBlocks = (N + TILE_M - 1) / TILE_M;
    const int aggBlocks  = (N + 7) / 8;

    // idx 0..2
    k_split <<<(N * DIM + 255) / 256, 256>>>(x, xhi, xlo, N * DIM);
    k_splitW<<<(R * DIM * DIM + 255) / 256, 256>>>(W1, whi, wlo, R);
    k_zero  <<<(N + 255) / 256, 256>>>(N);
    // idx 3: layer-1 tensor GEMM (ncu profiled slot)
    k_gemm_mma<<<gemmBlocks, 256, SM_TOT>>>(xhi, xlo, whi, wlo, q1, k1, N, R);
    // idx 4..6: CSR
    k_hist   <<<(E + 255) / 256, 256>>>(dst, E);
    k_scan   <<<1, 1024>>>(N);
    k_scatter<<<(E + 255) / 256, 256>>>(src, dst, et, E, N);
    // idx 7: layer-1 aggregation
    k_agg<<<aggBlocks, 256>>>(h1, b1, N, R, 0);
    // layer 2
    k_split <<<(N * DIM + 255) / 256, 256>>>(h1, xhi, xlo, N * DIM);
    k_splitW<<<(R * DIM * DIM + 255) / 256, 256>>>(W2, whi, wlo, R);
    k_gemm_mma<<<gemmBlocks, 256, SM_TOT>>>(xhi, xlo, whi, wlo, q2, k2, N, R);
    k_agg<<<aggBlocks, 256>>>(h2, b2, N, R, 1);
    // outputs
    k_alpha<<<(E + 255) / 256, 256>>>(dst, alpo, E);
    k_copy_edges<<<(2 * E + 255) / 256, 256>>>(ei, eidxo, 2 * E);
}

// round 7
// speedup vs baseline: 1.4305x; 1.0827x over previous
#include <cuda_runtime.h>
#include <cuda_bf16.h>
#include <cstdint>
#include <cmath>

#define DIM    64
#define MAXN   50000
#define MAXR   8
#define MAXE   800000
#define TILE_M 128
#define LDA    72          // padded smem row length (bf16 elems)

typedef uint32_t u32;

// ---------------- scratch (static device globals; no allocation) ----------------
__device__ __align__(256) float g_xw[(size_t)MAXR * MAXN * DIM];  // [R][N][64]
__device__ __align__(256) float g_h [(size_t)MAXN * DIM];
__device__ float g_qi[MAXN * MAXR];          // [n][r]
__device__ float g_kj[(size_t)MAXR * MAXN];  // [r][n]
__device__ float g_s [MAXN];
__device__ float g_e [MAXE];
// CSR
__device__ int   g_deg [MAXN];
__device__ int   g_cur [MAXN];
__device__ int   g_off [MAXN];
__device__ int   g_esrcr[MAXE];              // r*N + src  (== xw/kj row), sorted by dst
__device__ unsigned char g_er[MAXE];
__device__ int   g_eorig[MAXE];
// bf16 W splits
__device__ __nv_bfloat16 g_whi[MAXR * DIM * DIM];   // W^T: [r][o][k]
__device__ __nv_bfloat16 g_wlo[MAXR * DIM * DIM];

// W [R,64(k),64(o)] -> Wt [R,64(o),64(k)] split hi/lo
__global__ void k_splitW(const float* __restrict__ W, __nv_bfloat16* __restrict__ whi,
                         __nv_bfloat16* __restrict__ wlo, int R) {
    int i = blockIdx.x * blockDim.x + threadIdx.x;
    if (i >= R * DIM * DIM) return;
    int r = i >> 12, rem = i & 4095, o = rem >> 6, kk = rem & 63;
    float v = W[(r << 12) + kk * 64 + o];
    __nv_bfloat16 h = __float2bfloat16(v);
    whi[i] = h;
    wlo[i] = __float2bfloat16(v - __bfloat162float(h));
}

// ---------------- MMA + split helpers ----------------
__device__ __forceinline__ void mma16816(float* d, const u32* a, u32 b0, u32 b1) {
    asm volatile(
        "mma.sync.aligned.m16n8k16.row.col.f32.bf16.bf16.f32 "
        "{%0,%1,%2,%3}, {%4,%5,%6,%7}, {%8,%9}, {%0,%1,%2,%3};"
        : "+f"(d[0]), "+f"(d[1]), "+f"(d[2]), "+f"(d[3])
        : "r"(a[0]), "r"(a[1]), "r"(a[2]), "r"(a[3]), "r"(b0), "r"(b1));
}

// pack (x0,x1) -> bf16x2 hi (low half = x0); lo = bf16x2 of residual
__device__ __forceinline__ u32 bsplit(float x0, float x1, u32& lo) {
    u32 hi;
    asm("cvt.rn.bf16x2.f32 %0, %1, %2;" : "=r"(hi) : "f"(x1), "f"(x0));
    float h0 = __uint_as_float(hi << 16);
    float h1 = __uint_as_float(hi & 0xffff0000u);
    asm("cvt.rn.bf16x2.f32 %0, %1, %2;" : "=r"(lo) : "f"(x1 - h1), "f"(x0 - h0));
    return hi;
}

// ---------------- tensor GEMM: one (128-node tile, relation) per block --------
// xw[r][n][:] = X[n] @ W[r]; bf16 split (XhiWhi + XloWhi + XhiWlo), f32 accum.
// A fragments loaded from f32 X and split in registers. Fused qi/kj epilogue.
__global__ void __launch_bounds__(256, 4) k_gemm_mma(
        const float* __restrict__ X,
        const __nv_bfloat16* __restrict__ whi, const __nv_bfloat16* __restrict__ wlo,
        const float* __restrict__ qv, const float* __restrict__ kv, int N, int R) {
    __shared__ __nv_bfloat16 Bhi[64 * LDA], Blo[64 * LDA];
    __shared__ float sQ[64], sK[64];

    const int tid = threadIdx.x;
    const int w   = tid >> 5;
    const int lane = tid & 31;
    const int g   = lane >> 2;     // 0..7
    const int tig = lane & 3;      // 0..3
    const int r   = blockIdx.y;
    const int n0  = blockIdx.x * TILE_M;

    if (tid < 64) { sQ[tid] = qv[tid]; sK[tid] = kv[tid]; }
    // stage B = Wt[r] (hi, lo): 64 rows (o) x 64 (k)
    for (int i = tid; i < 512; i += 256) {
        int row = i >> 3, c8 = i & 7;
        uint4 vh = ((const uint4*)whi)[(size_t)r * 512 + i];
        uint4 vl = ((const uint4*)wlo)[(size_t)r * 512 + i];
        *(uint4*)&Bhi[row * LDA + c8 * 8] = vh;
        *(uint4*)&Blo[row * LDA + c8 * 8] = vl;
    }
    __syncthreads();

    const int nA = n0 + w * 16 + g;
    const int nB = nA + 8;
    const bool vA = nA < N, vB = nB < N;
    const float* xA = X + (size_t)nA * DIM;
    const float* xB = X + (size_t)nB * DIM;

    float d[8][4];
#pragma unroll
    for (int nt = 0; nt < 8; nt++)
#pragma unroll
        for (int j = 0; j < 4; j++) d[nt][j] = 0.f;

#pragma unroll
    for (int ks = 0; ks < 4; ks++) {
        const int kb = ks * 16;
        const int c = kb + 2 * tig;
        float2 z = make_float2(0.f, 0.f);
        float2 p0 = vA ? *(const float2*)(xA + c)     : z;
        float2 p1 = vB ? *(const float2*)(xB + c)     : z;
        float2 p2 = vA ? *(const float2*)(xA + c + 8) : z;
        float2 p3 = vB ? *(const float2*)(xB + c + 8) : z;
        u32 ahi[4], alo[4];
        ahi[0] = bsplit(p0.x, p0.y, alo[0]);
        ahi[1] = bsplit(p1.x, p1.y, alo[1]);
        ahi[2] = bsplit(p2.x, p2.y, alo[2]);
        ahi[3] = bsplit(p3.x, p3.y, alo[3]);
#pragma unroll
        for (int nt = 0; nt < 8; nt++) {
            int orow = nt * 8 + g;
            u32 b0h = *(const u32*)&Bhi[orow * LDA + kb + 2 * tig];
            u32 b1h = *(const u32*)&Bhi[orow * LDA + kb + 2 * tig + 8];
            mma16816(d[nt], ahi, b0h, b1h);
            mma16816(d[nt], alo, b0h, b1h);
            u32 b0l = *(const u32*)&Blo[orow * LDA + kb + 2 * tig];
            u32 b1l = *(const u32*)&Blo[orow * LDA + kb + 2 * tig + 8];
            mma16816(d[nt], ahi, b0l, b1l);
        }
    }

    // epilogue: store xw rows + fused qi/kj
    float pqA = 0.f, pkA = 0.f, pqB = 0.f, pkB = 0.f;
    float* baseA = g_xw + ((size_t)r * N + nA) * DIM;
    float* baseB = g_xw + ((size_t)r * N + nB) * DIM;
#pragma unroll
    for (int nt = 0; nt < 8; nt++) {
        int c = nt * 8 + 2 * tig;
        float q0 = sQ[c], q1 = sQ[c + 1], k0 = sK[c], k1 = sK[c + 1];
        pqA += d[nt][0] * q0 + d[nt][1] * q1;
        pkA += d[nt][0] * k0 + d[nt][1] * k1;
        pqB += d[nt][2] * q0 + d[nt][3] * q1;
        pkB += d[nt][2] * k0 + d[nt][3] * k1;
        if (vA) *(float2*)(baseA + c) = make_float2(d[nt][0], d[nt][1]);
        if (vB) *(float2*)(baseB + c) = make_float2(d[nt][2], d[nt][3]);
    }
    pqA += __shfl_xor_sync(0xffffffffu, pqA, 1);
    pqA += __shfl_xor_sync(0xffffffffu, pqA, 2);
    pkA += __shfl_xor_sync(0xffffffffu, pkA, 1);
    pkA += __shfl_xor_sync(0xffffffffu, pkA, 2);
    pqB += __shfl_xor_sync(0xffffffffu, pqB, 1);
    pqB += __shfl_xor_sync(0xffffffffu, pqB, 2);
    pkB += __shfl_xor_sync(0xffffffffu, pkB, 1);
    pkB += __shfl_xor_sync(0xffffffffu, pkB, 2);
    if (tig == 0) {
        if (vA) { g_qi[nA * R + r] = pqA; g_kj[(size_t)r * N + nA] = pkA; }
        if (vB) { g_qi[nB * R + r] = pqB; g_kj[(size_t)r * N + nB] = pkB; }
    }
}

// ---------------- CSR build ----------------
__global__ void k_zero(int N) {
    int i = blockIdx.x * blockDim.x + threadIdx.x;
    if (i < N) { g_deg[i] = 0; g_cur[i] = 0; }
}
__global__ void k_hist(const int* __restrict__ dst, int E) {
    int e = blockIdx.x * blockDim.x + threadIdx.x;
    if (e < E) atomicAdd(&g_deg[dst[e]], 1);
}
__global__ void k_scan(int N) {
    __shared__ int wsum[32];
    int tid = threadIdx.x;
    int per = (N + 1023) / 1024;
    int start = tid * per;
    int end = min(start + per, N);
    int local = 0;
    for (int i = start; i < end; i++) local += g_deg[i];
    int lane = tid & 31, w = tid >> 5;
    int v = local;
#pragma unroll
    for (int o = 1; o < 32; o <<= 1) {
        int u = __shfl_up_sync(0xffffffffu, v, o);
        if (lane >= o) v += u;
    }
    if (lane == 31) wsum[w] = v;
    __syncthreads();
    if (w == 0) {
        int s = wsum[lane];
#pragma unroll
        for (int o = 1; o < 32; o <<= 1) {
            int u = __shfl_up_sync(0xffffffffu, s, o);
            if (lane >= o) s += u;
        }
        wsum[lane] = s;
    }
    __syncthreads();
    int excl = v - local + (w > 0 ? wsum[w - 1] : 0);
    int run = excl;
    for (int i = start; i < end; i++) { g_off[i] = run; run += g_deg[i]; }
}
__global__ void k_scatter(const int* __restrict__ src, const int* __restrict__ dst,
                          const int* __restrict__ et, int E, int N) {
    int e = blockIdx.x * blockDim.x + threadIdx.x;
    if (e >= E) return;
    int d = dst[e];
    int pos = g_off[d] + atomicAdd(&g_cur[d], 1);
    int r = et[e];
    g_esrcr[pos] = r * N + src[e];
    g_er[pos]    = (unsigned char)r;
    g_eorig[pos] = e;
}

// ---------------- fused aggregation: warp per destination node ----------------
__global__ void k_agg(float* __restrict__ out, const float* __restrict__ bias,
                      int N, int R, int store_e) {
    int d = (blockIdx.x * blockDim.x + threadIdx.x) >> 5;
    int lane = threadIdx.x & 31;
    if (d >= N) return;
    int beg = g_off[d];
    int deg = g_deg[d];
    const float* qrow = g_qi + d * R;

    float acc0 = 0.f, acc1 = 0.f, s = 0.f;

    for (int base = 0; base < deg; base += 4) {
        int vv[4], rr[4];
#pragma unroll
        for (int j = 0; j < 4; j++) {
            int idx = beg + min(base + j, deg - 1);
            vv[j] = g_esrcr[idx];
            rr[j] = (int)g_er[idx];
        }
        float ev[4];
#pragma unroll
        for (int j = 0; j < 4; j++) {
            float l = qrow[rr[j]] + g_kj[vv[j]];
            l = (l >= 0.f) ? l : 0.2f * l;
            float e = __expf(l);
            ev[j] = (base + j < deg) ? e : 0.f;
            s += ev[j];
        }
#pragma unroll
        for (int j = 0; j < 4; j++) {
            float2 xv = *(const float2*)&g_xw[(size_t)vv[j] * DIM + lane * 2];
            acc0 += ev[j] * xv.x;
            acc1 += ev[j] * xv.y;
        }
        if (store_e && lane == 0) {
#pragma unroll
            for (int j = 0; j < 4; j++)
                if (base + j < deg) g_e[g_eorig[beg + base + j]] = ev[j];
        }
    }

    if (lane == 0) g_s[d] = s;
    float inv = 1.f / (s + 1e-16f);
    int c = lane * 2;
    float2 o;
    o.x = fmaxf(acc0 * inv + bias[c],     0.f);
    o.y = fmaxf(acc1 * inv + bias[c + 1], 0.f);
    *(float2*)&out[(size_t)d * DIM + c] = o;
}

__global__ void k_alpha(const int* __restrict__ dst, float* __restrict__ alpha, int E) {
    int e = blockIdx.x * blockDim.x + threadIdx.x;
    if (e >= E) return;
    alpha[e] = g_e[e] / (g_s[dst[e]] + 1e-16f);
}
__global__ void k_copy_edges(const int* __restrict__ ei, float* __restrict__ out, int n2e) {
    int i = blockIdx.x * blockDim.x + threadIdx.x;
    if (i < n2e) out[i] = (float)ei[i];
}

// ---------------- host orchestration ----------------
extern "C" void kernel_launch(void* const* d_in, const int* in_sizes, int n_in,
                              void* d_out, int out_size) {
    const float* x   = (const float*)d_in[0];
    const int*   ei  = (const int*)d_in[1];
    const int*   et  = (const int*)d_in[2];
    const float* W1  = (const float*)d_in[3];
    const float* q1  = (const float*)d_in[4];
    const float* k1  = (const float*)d_in[5];
    const float* b1  = (const float*)d_in[6];
    const float* W2  = (const float*)d_in[7];
    const float* q2  = (const float*)d_in[8];
    const float* k2  = (const float*)d_in[9];
    const float* b2  = (const float*)d_in[10];

    const int N = in_sizes[0] / DIM;
    const int E = in_sizes[2];
    const int R = in_sizes[3] / (DIM * DIM);

    const int* src = ei;
    const int* dst = ei + E;

    float* h1;  cudaGetSymbolAddress((void**)&h1, g_h);
    __nv_bfloat16 *whi, *wlo;
    cudaGetSymbolAddress((void**)&whi, g_whi);
    cudaGetSymbolAddress((void**)&wlo, g_wlo);

    float* outf  = (float*)d_out;
    float* h2    = outf;
    float* eidxo = outf + (size_t)N * DIM;
    float* alpo  = eidxo + 2 * (size_t)E;

    const dim3 gemmGrid((N + TILE_M - 1) / TILE_M, R);
    const int aggBlocks = (N + 7) / 8;

    // idx 0..2
    k_zero  <<<(N + 255) / 256, 256>>>(N);
    k_hist  <<<(E + 255) / 256, 256>>>(dst, E);
    k_splitW<<<(R * DIM * DIM + 255) / 256, 256>>>(W1, whi, wlo, R);
    // idx 3: layer-1 tensor GEMM (ncu profiled slot)
    k_gemm_mma<<<gemmGrid, 256>>>(x, whi, wlo, q1, k1, N, R);
    // idx 4..5: CSR
    k_scan   <<<1, 1024>>>(N);
    k_scatter<<<(E + 255) / 256, 256>>>(src, dst, et, E, N);
    // idx 6: layer-1 aggregation
    k_agg<<<aggBlocks, 256>>>(h1, b1, N, R, 0);
    // layer 2
    k_splitW<<<(R * DIM * DIM + 255) / 256, 256>>>(W2, whi, wlo, R);
    k_gemm_mma<<<gemmGrid, 256>>>(h1, whi, wlo, q2, k2, N, R);
    k_agg<<<aggBlocks, 256>>>(h2, b2, N, R, 1);
    // outputs
    k_alpha<<<(E + 255) / 256, 256>>>(dst, alpo, E);
    k_copy_edges<<<(2 * E + 255) / 256, 256>>>(ei, eidxo, 2 * E);
}

// round 8
// speedup vs baseline: 1.4674x; 1.0258x over previous
#include <cuda_runtime.h>
#include <cuda_bf16.h>
#include <cuda_fp16.h>
#include <cstdint>
#include <cmath>

#define DIM    64
#define MAXN   50000
#define MAXR   8
#define MAXE   800000
#define TILE_M 128
#define LDA    72          // padded smem row length (bf16 elems); 144B rows, 16B-aligned

typedef uint32_t u32;

// ---------------- scratch (static device globals; no allocation) ----------------
__device__ __align__(256) __half g_xw16[(size_t)MAXR * MAXN * DIM];  // [R][N][64] fp16
__device__ __align__(256) float  g_h [(size_t)MAXN * DIM];
__device__ float g_qi[MAXN * MAXR];          // [n][r]
__device__ float g_kj[(size_t)MAXR * MAXN];  // [r][n]
__device__ float g_s [MAXN];
__device__ float g_e [MAXE];
// CSR
__device__ int   g_deg [MAXN];
__device__ int   g_cur [MAXN];
__device__ int   g_off [MAXN];
__device__ int   g_esrcr[MAXE];              // r*N + src  (== xw/kj row), sorted by dst
__device__ unsigned char g_er[MAXE];
__device__ int   g_eorig[MAXE];
// bf16 W splits
__device__ __nv_bfloat16 g_whi[MAXR * DIM * DIM];   // W^T: [r][o][k]
__device__ __nv_bfloat16 g_wlo[MAXR * DIM * DIM];

// W [R,64(k),64(o)] -> Wt [R,64(o),64(k)] split hi/lo
__global__ void k_splitW(const float* __restrict__ W, __nv_bfloat16* __restrict__ whi,
                         __nv_bfloat16* __restrict__ wlo, int R) {
    int i = blockIdx.x * blockDim.x + threadIdx.x;
    if (i >= R * DIM * DIM) return;
    int r = i >> 12, rem = i & 4095, o = rem >> 6, kk = rem & 63;
    float v = W[(r << 12) + kk * 64 + o];
    __nv_bfloat16 h = __float2bfloat16(v);
    whi[i] = h;
    wlo[i] = __float2bfloat16(v - __bfloat162float(h));
}

// ---------------- MMA + split helpers ----------------
__device__ __forceinline__ void mma16816(float* d, const u32* a, u32 b0, u32 b1) {
    asm volatile(
        "mma.sync.aligned.m16n8k16.row.col.f32.bf16.bf16.f32 "
        "{%0,%1,%2,%3}, {%4,%5,%6,%7}, {%8,%9}, {%0,%1,%2,%3};"
        : "+f"(d[0]), "+f"(d[1]), "+f"(d[2]), "+f"(d[3])
        : "r"(a[0]), "r"(a[1]), "r"(a[2]), "r"(a[3]), "r"(b0), "r"(b1));
}

__device__ __forceinline__ void ldmx4(u32* b, u32 addr) {
    asm volatile("ldmatrix.sync.aligned.m8n8.x4.shared.b16 {%0,%1,%2,%3}, [%4];"
                 : "=r"(b[0]), "=r"(b[1]), "=r"(b[2]), "=r"(b[3]) : "r"(addr));
}

// pack (x0,x1) -> bf16x2 hi (low half = x0); lo = bf16x2 of residual
__device__ __forceinline__ u32 bsplit(float x0, float x1, u32& lo) {
    u32 hi;
    asm("cvt.rn.bf16x2.f32 %0, %1, %2;" : "=r"(hi) : "f"(x1), "f"(x0));
    float h0 = __uint_as_float(hi << 16);
    float h1 = __uint_as_float(hi & 0xffff0000u);
    asm("cvt.rn.bf16x2.f32 %0, %1, %2;" : "=r"(lo) : "f"(x1 - h1), "f"(x0 - h0));
    return hi;
}

// ---------------- tensor GEMM: one (128-node tile, relation) per block --------
// xw[r][n][:] = X[n] @ W[r]; bf16 split (XhiWhi + XloWhi + XhiWlo), f32 accum.
// A fragments from f32 X, split in registers. B fragments via ldmatrix.x4.
// Outputs: xw in fp16, fused qi/kj in f32.
__global__ void __launch_bounds__(256, 4) k_gemm_mma(
        const float* __restrict__ X,
        const __nv_bfloat16* __restrict__ whi, const __nv_bfloat16* __restrict__ wlo,
        const float* __restrict__ qv, const float* __restrict__ kv, int N, int R) {
    __shared__ __align__(16) __nv_bfloat16 Bhi[64 * LDA], Blo[64 * LDA];
    __shared__ float sQ[64], sK[64];

    const int tid = threadIdx.x;
    const int w   = tid >> 5;
    const int lane = tid & 31;
    const int g   = lane >> 2;     // 0..7
    const int tig = lane & 3;      // 0..3
    const int r   = blockIdx.y;
    const int n0  = blockIdx.x * TILE_M;

    if (tid < 64) { sQ[tid] = qv[tid]; sK[tid] = kv[tid]; }
    // stage B = Wt[r] (hi, lo): 64 rows (o) x 64 (k)
    for (int i = tid; i < 512; i += 256) {
        int row = i >> 3, c8 = i & 7;
        uint4 vh = ((const uint4*)whi)[(size_t)r * 512 + i];
        uint4 vl = ((const uint4*)wlo)[(size_t)r * 512 + i];
        *(uint4*)&Bhi[row * LDA + c8 * 8] = vh;
        *(uint4*)&Blo[row * LDA + c8 * 8] = vl;
    }
    __syncthreads();

    const int nA = n0 + w * 16 + g;
    const int nB = nA + 8;
    const bool vA = nA < N, vB = nB < N;
    const float* xA = X + (size_t)nA * DIM;
    const float* xB = X + (size_t)nB * DIM;

    // ldmatrix per-lane address parts: tile t = lane>>3 (0..3), row-in-tile = lane&7
    const int lt  = lane >> 3;
    const int lrw = lane & 7;
    const int rowsel = (lt >> 1) * 8 + lrw;     // row within 16-row (two-tile) group
    const int colsel = (lt & 1) * 8;            // k-half
    const u32 bhiBase = (u32)__cvta_generic_to_shared(Bhi);
    const u32 bloBase = (u32)__cvta_generic_to_shared(Blo);

    float d[8][4];
#pragma unroll
    for (int nt = 0; nt < 8; nt++)
#pragma unroll
        for (int j = 0; j < 4; j++) d[nt][j] = 0.f;

#pragma unroll
    for (int ks = 0; ks < 4; ks++) {
        const int kb = ks * 16;
        const int c = kb + 2 * tig;
        float2 z = make_float2(0.f, 0.f);
        float2 p0 = vA ? *(const float2*)(xA + c)     : z;
        float2 p1 = vB ? *(const float2*)(xB + c)     : z;
        float2 p2 = vA ? *(const float2*)(xA + c + 8) : z;
        float2 p3 = vB ? *(const float2*)(xB + c + 8) : z;
        u32 ahi[4], alo[4];
        ahi[0] = bsplit(p0.x, p0.y, alo[0]);
        ahi[1] = bsplit(p1.x, p1.y, alo[1]);
        ahi[2] = bsplit(p2.x, p2.y, alo[2]);
        ahi[3] = bsplit(p3.x, p3.y, alo[3]);

#pragma unroll
        for (int m = 0; m < 4; m++) {     // m covers nt = 2m, 2m+1
            u32 off = (u32)(((m * 16 + rowsel) * LDA + kb + colsel) * 2);
            u32 bh[4], bl[4];
            ldmx4(bh, bhiBase + off);
            ldmx4(bl, bloBase + off);
            mma16816(d[2 * m],     ahi, bh[0], bh[1]);
            mma16816(d[2 * m],     alo, bh[0], bh[1]);
            mma16816(d[2 * m],     ahi, bl[0], bl[1]);
            mma16816(d[2 * m + 1], ahi, bh[2], bh[3]);
            mma16816(d[2 * m + 1], alo, bh[2], bh[3]);
            mma16816(d[2 * m + 1], ahi, bl[2], bl[3]);
        }
    }

    // epilogue: fp16 xw stores + fused qi/kj (f32)
    float pqA = 0.f, pkA = 0.f, pqB = 0.f, pkB = 0.f;
    __half* baseA = g_xw16 + ((size_t)r * N + nA) * DIM;
    __half* baseB = g_xw16 + ((size_t)r * N + nB) * DIM;
#pragma unroll
    for (int nt = 0; nt < 8; nt++) {
        int c = nt * 8 + 2 * tig;
        float q0 = sQ[c], q1 = sQ[c + 1], k0 = sK[c], k1 = sK[c + 1];
        pqA += d[nt][0] * q0 + d[nt][1] * q1;
        pkA += d[nt][0] * k0 + d[nt][1] * k1;
        pqB += d[nt][2] * q0 + d[nt][3] * q1;
        pkB += d[nt][2] * k0 + d[nt][3] * k1;
        if (vA) *(__half2*)(baseA + c) = __floats2half2_rn(d[nt][0], d[nt][1]);
        if (vB) *(__half2*)(baseB + c) = __floats2half2_rn(d[nt][2], d[nt][3]);
    }
    pqA += __shfl_xor_sync(0xffffffffu, pqA, 1);
    pqA += __shfl_xor_sync(0xffffffffu, pqA, 2);
    pkA += __shfl_xor_sync(0xffffffffu, pkA, 1);
    pkA += __shfl_xor_sync(0xffffffffu, pkA, 2);
    pqB += __shfl_xor_sync(0xffffffffu, pqB, 1);
    pqB += __shfl_xor_sync(0xffffffffu, pqB, 2);
    pkB += __shfl_xor_sync(0xffffffffu, pkB, 1);
    pkB += __shfl_xor_sync(0xffffffffu, pkB, 2);
    if (tig == 0) {
        if (vA) { g_qi[nA * R + r] = pqA; g_kj[(size_t)r * N + nA] = pkA; }
        if (vB) { g_qi[nB * R + r] = pqB; g_kj[(size_t)r * N + nB] = pkB; }
    }
}

// ---------------- CSR build ----------------
__global__ void k_zero(int N) {
    int i = blockIdx.x * blockDim.x + threadIdx.x;
    if (i < N) { g_deg[i] = 0; g_cur[i] = 0; }
}
__global__ void k_hist(const int* __restrict__ dst, int E) {
    int e = blockIdx.x * blockDim.x + threadIdx.x;
    if (e < E) atomicAdd(&g_deg[dst[e]], 1);
}
__global__ void k_scan(int N) {
    __shared__ int wsum[32];
    int tid = threadIdx.x;
    int per = (N + 1023) / 1024;
    int start = tid * per;
    int end = min(start + per, N);
    int local = 0;
    for (int i = start; i < end; i++) local += g_deg[i];
    int lane = tid & 31, w = tid >> 5;
    int v = local;
#pragma unroll
    for (int o = 1; o < 32; o <<= 1) {
        int u = __shfl_up_sync(0xffffffffu, v, o);
        if (lane >= o) v += u;
    }
    if (lane == 31) wsum[w] = v;
    __syncthreads();
    if (w == 0) {
        int s = wsum[lane];
#pragma unroll
        for (int o = 1; o < 32; o <<= 1) {
            int u = __shfl_up_sync(0xffffffffu, s, o);
            if (lane >= o) s += u;
        }
        wsum[lane] = s;
    }
    __syncthreads();
    int excl = v - local + (w > 0 ? wsum[w - 1] : 0);
    int run = excl;
    for (int i = start; i < end; i++) { g_off[i] = run; run += g_deg[i]; }
}
__global__ void k_scatter(const int* __restrict__ src, const int* __restrict__ dst,
                          const int* __restrict__ et, int E, int N) {
    int e = blockIdx.x * blockDim.x + threadIdx.x;
    if (e >= E) return;
    int d = dst[e];
    int pos = g_off[d] + atomicAdd(&g_cur[d], 1);
    int r = et[e];
    g_esrcr[pos] = r * N + src[e];
    g_er[pos]    = (unsigned char)r;
    g_eorig[pos] = e;
}

// ---------------- fused aggregation: warp per destination node ----------------
__global__ void k_agg(float* __restrict__ out, const float* __restrict__ bias,
                      int N, int R, int store_e) {
    int d = (blockIdx.x * blockDim.x + threadIdx.x) >> 5;
    int lane = threadIdx.x & 31;
    if (d >= N) return;
    int beg = g_off[d];
    int deg = g_deg[d];
    const float* qrow = g_qi + d * R;

    float acc0 = 0.f, acc1 = 0.f, s = 0.f;

    for (int base = 0; base < deg; base += 4) {
        int vv[4], rr[4];
#pragma unroll
        for (int j = 0; j < 4; j++) {
            int idx = beg + min(base + j, deg - 1);
            vv[j] = g_esrcr[idx];
            rr[j] = (int)g_er[idx];
        }
        float ev[4];
#pragma unroll
        for (int j = 0; j < 4; j++) {
            float l = qrow[rr[j]] + g_kj[vv[j]];
            l = (l >= 0.f) ? l : 0.2f * l;
            float e = __expf(l);
            ev[j] = (base + j < deg) ? e : 0.f;
            s += ev[j];
        }
#pragma unroll
        for (int j = 0; j < 4; j++) {
            const __half2* row = (const __half2*)(g_xw16 + (size_t)vv[j] * DIM);
            float2 xv = __half22float2(row[lane]);
            acc0 += ev[j] * xv.x;
            acc1 += ev[j] * xv.y;
        }
        if (store_e && lane == 0) {
#pragma unroll
            for (int j = 0; j < 4; j++)
                if (base + j < deg) g_e[g_eorig[beg + base + j]] = ev[j];
        }
    }

    if (lane == 0) g_s[d] = s;
    float inv = 1.f / (s + 1e-16f);
    int c = lane * 2;
    float2 o;
    o.x = fmaxf(acc0 * inv + bias[c],     0.f);
    o.y = fmaxf(acc1 * inv + bias[c + 1], 0.f);
    *(float2*)&out[(size_t)d * DIM + c] = o;
}

__global__ void k_alpha(const int* __restrict__ dst, float* __restrict__ alpha, int E) {
    int e = blockIdx.x * blockDim.x + threadIdx.x;
    if (e >= E) return;
    alpha[e] = g_e[e] / (g_s[dst[e]] + 1e-16f);
}
__global__ void k_copy_edges(const int* __restrict__ ei, float* __restrict__ out, int n2e) {
    int i = blockIdx.x * blockDim.x + threadIdx.x;
    if (i < n2e) out[i] = (float)ei[i];
}

// ---------------- host orchestration ----------------
extern "C" void kernel_launch(void* const* d_in, const int* in_sizes, int n_in,
                              void* d_out, int out_size) {
    const float* x   = (const float*)d_in[0];
    const int*   ei  = (const int*)d_in[1];
    const int*   et  = (const int*)d_in[2];
    const float* W1  = (const float*)d_in[3];
    const float* q1  = (const float*)d_in[4];
    const float* k1  = (const float*)d_in[5];
    const float* b1  = (const float*)d_in[6];
    const float* W2  = (const float*)d_in[7];
    const float* q2  = (const float*)d_in[8];
    const float* k2  = (const float*)d_in[9];
    const float* b2  = (const float*)d_in[10];

    const int N = in_sizes[0] / DIM;
    const int E = in_sizes[2];
    const int R = in_sizes[3] / (DIM * DIM);

    const int* src = ei;
    const int* dst = ei + E;

    float* h1;  cudaGetSymbolAddress((void**)&h1, g_h);
    __nv_bfloat16 *whi, *wlo;
    cudaGetSymbolAddress((void**)&whi, g_whi);
    cudaGetSymbolAddress((void**)&wlo, g_wlo);

    float* outf  = (float*)d_out;
    float* h2    = outf;
    float* eidxo = outf + (size_t)N * DIM;
    float* alpo  = eidxo + 2 * (size_t)E;

    const dim3 gemmGrid((N + TILE_M - 1) / TILE_M, R);
    const int aggBlocks = (N + 7) / 8;

    // idx 0..2
    k_zero  <<<(N + 255) / 256, 256>>>(N);
    k_hist  <<<(E + 255) / 256, 256>>>(dst, E);
    k_splitW<<<(R * DIM * DIM + 255) / 256, 256>>>(W1, whi, wlo, R);
    // idx 3: layer-1 tensor GEMM (ncu profiled slot)
    k_gemm_mma<<<gemmGrid, 256>>>(x, whi, wlo, q1, k1, N, R);
    // idx 4..5: CSR
    k_scan   <<<1, 1024>>>(N);
    k_scatter<<<(E + 255) / 256, 256>>>(src, dst, et, E, N);
    // idx 6: layer-1 aggregation
    k_agg<<<aggBlocks, 256>>>(h1, b1, N, R, 0);
    // layer 2
    k_splitW<<<(R * DIM * DIM + 255) / 256, 256>>>(W2, whi, wlo, R);
    k_gemm_mma<<<gemmGrid, 256>>>(h1, whi, wlo, q2, k2, N, R);
    k_agg<<<aggBlocks, 256>>>(h2, b2, N, R, 1);
    // outputs
    k_alpha<<<(E + 255) / 256, 256>>>(dst, alpo, E);
    k_copy_edges<<<(2 * E + 255) / 256, 256>>>(ei, eidxo, 2 * E);
}

// round 9
// speedup vs baseline: 1.5885x; 1.0825x over previous
#include <cuda_runtime.h>
#include <cuda_bf16.h>
#include <cuda_fp16.h>
#include <cstdint>
#include <cmath>

#define DIM    64
#define MAXN   50000
#define MAXR   8
#define MAXE   800000
#define TILE_M 128
#define LDAH   72            // padded row length in bf16/half elems (144B rows)

typedef uint32_t u32;

// ---------------- scratch (static device globals; no allocation) ----------------
__device__ __align__(256) __half g_xw16[(size_t)MAXR * MAXN * DIM];  // [R][N][64]
__device__ float g_qi[MAXN * MAXR];          // [n][r]
__device__ float g_kj[(size_t)MAXR * MAXN];  // [r][n]
__device__ float g_s [MAXN];
__device__ float g_e [MAXE];
// CSR
__device__ int   g_deg [MAXN];
__device__ int   g_cur [MAXN];
__device__ int   g_off [MAXN];
__device__ u32   g_epk [MAXE];               // (r<<16)|src, sorted by dst
__device__ int   g_eorig[MAXE];
// bf16 splits of current layer input + W^T
__device__ __align__(256) __nv_bfloat16 g_xhi[(size_t)MAXN * DIM];
__device__ __align__(256) __nv_bfloat16 g_xlo[(size_t)MAXN * DIM];
__device__ __align__(256) __nv_bfloat16 g_whi[MAXR * DIM * DIM];   // [r][o][k]
__device__ __align__(256) __nv_bfloat16 g_wlo[MAXR * DIM * DIM];

// ---------------- helpers ----------------
__device__ __forceinline__ void mma16816(float* d, const u32* a, u32 b0, u32 b1) {
    asm volatile(
        "mma.sync.aligned.m16n8k16.row.col.f32.bf16.bf16.f32 "
        "{%0,%1,%2,%3}, {%4,%5,%6,%7}, {%8,%9}, {%0,%1,%2,%3};"
        : "+f"(d[0]), "+f"(d[1]), "+f"(d[2]), "+f"(d[3])
        : "r"(a[0]), "r"(a[1]), "r"(a[2]), "r"(a[3]), "r"(b0), "r"(b1));
}
__device__ __forceinline__ void ldmx4(u32* b, u32 addr) {
    asm volatile("ldmatrix.sync.aligned.m8n8.x4.shared.b16 {%0,%1,%2,%3}, [%4];"
                 : "=r"(b[0]), "=r"(b[1]), "=r"(b[2]), "=r"(b[3]) : "r"(addr));
}
__device__ __forceinline__ void cp16(u32 dst, const void* src) {
    asm volatile("cp.async.ca.shared.global [%0], [%1], 16;" :: "r"(dst), "l"(src));
}
#define CP_COMMIT() asm volatile("cp.async.commit_group;" ::: "memory")
#define CP_WAIT0()  asm volatile("cp.async.wait_group 0;" ::: "memory")

// pack (x0,x1) -> bf16x2 hi (low half = x0); lo = bf16x2 of residual
__device__ __forceinline__ u32 bsplit(float x0, float x1, u32& lo) {
    u32 hi;
    asm("cvt.rn.bf16x2.f32 %0, %1, %2;" : "=r"(hi) : "f"(x1), "f"(x0));
    float h0 = __uint_as_float(hi << 16);
    float h1 = __uint_as_float(hi & 0xffff0000u);
    asm("cvt.rn.bf16x2.f32 %0, %1, %2;" : "=r"(lo) : "f"(x1 - h1), "f"(x0 - h0));
    return hi;
}

// ---------------- prep: split x (elementwise) + split/transpose W -------------
__global__ void k_prep(const float* __restrict__ x, const float* __restrict__ W,
                       int nx, int nw, int R) {
    int i = blockIdx.x * blockDim.x + threadIdx.x;
    if (i < nx) {
        float v = x[i];
        __nv_bfloat16 h = __float2bfloat16(v);
        g_xhi[i] = h;
        g_xlo[i] = __float2bfloat16(v - __bfloat162float(h));
    } else if (i < nx + nw) {
        int j = i - nx;
        int r = j >> 12, rem = j & 4095, o = rem >> 6, kk = rem & 63;
        float v = W[(r << 12) + kk * 64 + o];
        __nv_bfloat16 h = __float2bfloat16(v);
        g_whi[j] = h;
        g_wlo[j] = __float2bfloat16(v - __bfloat162float(h));
    }
}
__global__ void k_splitW(const float* __restrict__ W, int R) {
    int i = blockIdx.x * blockDim.x + threadIdx.x;
    if (i >= R * DIM * DIM) return;
    int r = i >> 12, rem = i & 4095, o = rem >> 6, kk = rem & 63;
    float v = W[(r << 12) + kk * 64 + o];
    __nv_bfloat16 h = __float2bfloat16(v);
    g_whi[i] = h;
    g_wlo[i] = __float2bfloat16(v - __bfloat162float(h));
}

// ---------------- SMEM layout for gemm (bytes) ----------------
#define SM_AHI  0
#define SM_ALO  18432
#define SM_BHI  36864
#define SM_BLO  46080
#define SM_EPI  36864            // reuses B region after fragments consumed
#define SM_Q    55296
#define SM_K    55552
#define SM_QI   55808
#define SM_KI   56320
#define SM_TOT  56832

// ---------------- tensor GEMM: 128-node tile x 2 relations per block ----------
// warps: wm = w&3 (row group of 32), wn = w>>2 (col group of 32)
__global__ void __launch_bounds__(256, 3) k_gemm_mma(
        const float* __restrict__ qv, const float* __restrict__ kv, int N, int R) {
    extern __shared__ char sm[];
    const int tid = threadIdx.x;
    const int w = tid >> 5, lane = tid & 31;
    const int wm = w & 3, wn = w >> 2;
    const int g = lane >> 2, tig = lane & 3;
    const int lt = lane >> 3, lrw = lane & 7;
    const int n0 = blockIdx.x * TILE_M;
    const int r0 = blockIdx.y * 2;

    const u32 smb = (u32)__cvta_generic_to_shared(sm);

    // stage A tiles (hi/lo) via cp.async, rows clamped
    for (int i = tid; i < 1024; i += 256) {
        int row = i >> 3, ch = i & 7;
        int n = min(n0 + row, N - 1);
        cp16(smb + SM_AHI + row * 144 + ch * 16, g_xhi + (size_t)n * DIM + ch * 8);
        cp16(smb + SM_ALO + row * 144 + ch * 16, g_xlo + (size_t)n * DIM + ch * 8);
    }
    // stage B tiles for relation r0
    for (int i = tid; i < 512; i += 256) {
        int row = i >> 3, ch = i & 7;
        cp16(smb + SM_BHI + row * 144 + ch * 16, g_whi + ((size_t)r0 * 64 + row) * DIM + ch * 8);
        cp16(smb + SM_BLO + row * 144 + ch * 16, g_wlo + ((size_t)r0 * 64 + row) * DIM + ch * 8);
    }
    CP_COMMIT();
    if (tid < 64) {
        *(float*)(sm + SM_Q + tid * 4) = qv[tid];
        *(float*)(sm + SM_K + tid * 4) = kv[tid];
    }
    CP_WAIT0();
    __syncthreads();

    const float* sQ = (const float*)(sm + SM_Q);
    const float* sK = (const float*)(sm + SM_K);
    float* sQi = (float*)(sm + SM_QI);
    float* sKi = (float*)(sm + SM_KI);

    // ldmatrix lane addresses (byte offsets within tile, row-part varies by mt/np/kb)
    const int arow = wm * 32 + (lt & 1) * 8 + lrw;   // + mt*16
    const int acol = (lt >> 1) * 8;                   // + kb
    const int brow = wn * 32 + (lt >> 1) * 8 + lrw;   // + np*16
    const int bcol = (lt & 1) * 8;                    // + kb

    for (int rr = 0; rr < 2; rr++) {
        const int r = r0 + rr;

        float d[2][4][4];
#pragma unroll
        for (int mt = 0; mt < 2; mt++)
#pragma unroll
            for (int nt = 0; nt < 4; nt++)
#pragma unroll
                for (int j = 0; j < 4; j++) d[mt][nt][j] = 0.f;

#pragma unroll
        for (int ks = 0; ks < 4; ks++) {
            const int kb = ks * 16;
            u32 ahi[2][4], alo[2][4];
#pragma unroll
            for (int mt = 0; mt < 2; mt++) {
                u32 aoff = (u32)((arow + mt * 16) * 144 + (acol + kb) * 2);
                ldmx4(ahi[mt], smb + SM_AHI + aoff);
                ldmx4(alo[mt], smb + SM_ALO + aoff);
            }
#pragma unroll
            for (int np = 0; np < 2; np++) {
                u32 boff = (u32)((brow + np * 16) * 144 + (bcol + kb) * 2);
                u32 bh[4], bl[4];
                ldmx4(bh, smb + SM_BHI + boff);
                ldmx4(bl, smb + SM_BLO + boff);
#pragma unroll
                for (int mt = 0; mt < 2; mt++) {
                    mma16816(d[mt][2 * np],     ahi[mt], bh[0], bh[1]);
                    mma16816(d[mt][2 * np],     alo[mt], bh[0], bh[1]);
                    mma16816(d[mt][2 * np],     ahi[mt], bl[0], bl[1]);
                    mma16816(d[mt][2 * np + 1], ahi[mt], bh[2], bh[3]);
                    mma16816(d[mt][2 * np + 1], alo[mt], bh[2], bh[3]);
                    mma16816(d[mt][2 * np + 1], ahi[mt], bl[2], bl[3]);
                }
            }
        }

        // ---- epilogue: stage fp16 tile in smem (B region), reduce qi/kj ----
        __syncthreads();                       // B fragments fully consumed
        if (tid < 128) { sQi[tid] = 0.f; sKi[tid] = 0.f; }
        __syncthreads();

        __half* epi = (__half*)(sm + SM_EPI);
#pragma unroll
        for (int mt = 0; mt < 2; mt++) {
            int rA = wm * 32 + mt * 16 + g;
            int rB = rA + 8;
            float pqA = 0.f, pkA = 0.f, pqB = 0.f, pkB = 0.f;
#pragma unroll
            for (int nt = 0; nt < 4; nt++) {
                int c = wn * 32 + nt * 8 + 2 * tig;
                float q0 = sQ[c], q1 = sQ[c + 1], k0 = sK[c], k1 = sK[c + 1];
                pqA += d[mt][nt][0] * q0 + d[mt][nt][1] * q1;
                pkA += d[mt][nt][0] * k0 + d[mt][nt][1] * k1;
                pqB += d[mt][nt][2] * q0 + d[mt][nt][3] * q1;
                pkB += d[mt][nt][2] * k0 + d[mt][nt][3] * k1;
                *(__half2*)&epi[rA * LDAH + c] = __floats2half2_rn(d[mt][nt][0], d[mt][nt][1]);
                *(__half2*)&epi[rB * LDAH + c] = __floats2half2_rn(d[mt][nt][2], d[mt][nt][3]);
            }
            pqA += __shfl_xor_sync(0xffffffffu, pqA, 1);
            pqA += __shfl_xor_sync(0xffffffffu, pqA, 2);
            pkA += __shfl_xor_sync(0xffffffffu, pkA, 1);
            pkA += __shfl_xor_sync(0xffffffffu, pkA, 2);
            pqB += __shfl_xor_sync(0xffffffffu, pqB, 1);
            pqB += __shfl_xor_sync(0xffffffffu, pqB, 2);
            pkB += __shfl_xor_sync(0xffffffffu, pkB, 1);
            pkB += __shfl_xor_sync(0xffffffffu, pkB, 2);
            if (tig == 0) {
                atomicAdd(&sQi[rA], pqA);
                atomicAdd(&sKi[rA], pkA);
                atomicAdd(&sQi[rB], pqB);
                atomicAdd(&sKi[rB], pkB);
            }
        }
        __syncthreads();

        // coalesced writeout of xw16
        for (int i = tid; i < 1024; i += 256) {
            int row = i >> 3, ch = i & 7;
            int n = n0 + row;
            if (n < N) {
                uint4 v = *(uint4*)((char*)epi + row * 144 + ch * 16);
                *(uint4*)(g_xw16 + ((size_t)r * N + n) * DIM + ch * 8) = v;
            }
        }
        if (tid < 128) {
            int n = n0 + tid;
            if (n < N) {
                g_qi[n * R + r] = sQi[tid];
                g_kj[(size_t)r * N + n] = sKi[tid];
            }
        }

        // restage B for next relation (epi buffer == B region)
        if (rr == 0) {
            __syncthreads();
            for (int i = tid; i < 512; i += 256) {
                int row = i >> 3, ch = i & 7;
                cp16(smb + SM_BHI + row * 144 + ch * 16,
                     g_whi + ((size_t)(r0 + 1) * 64 + row) * DIM + ch * 8);
                cp16(smb + SM_BLO + row * 144 + ch * 16,
                     g_wlo + ((size_t)(r0 + 1) * 64 + row) * DIM + ch * 8);
            }
            CP_COMMIT();
            CP_WAIT0();
            __syncthreads();
        }
    }
}

// ---------------- CSR build ----------------
__global__ void k_zero(int N) {
    int i = blockIdx.x * blockDim.x + threadIdx.x;
    if (i < N) { g_deg[i] = 0; g_cur[i] = 0; }
}
__global__ void k_hist(const int* __restrict__ dst, int E) {
    int e = blockIdx.x * blockDim.x + threadIdx.x;
    if (e < E) atomicAdd(&g_deg[dst[e]], 1);
}
__global__ void k_scan(int N) {
    __shared__ int wsum[32];
    int tid = threadIdx.x;
    int per = (N + 1023) / 1024;
    int start = tid * per;
    int end = min(start + per, N);
    int local = 0;
    for (int i = start; i < end; i++) local += g_deg[i];
    int lane = tid & 31, w = tid >> 5;
    int v = local;
#pragma unroll
    for (int o = 1; o < 32; o <<= 1) {
        int u = __shfl_up_sync(0xffffffffu, v, o);
        if (lane >= o) v += u;
    }
    if (lane == 31) wsum[w] = v;
    __syncthreads();
    if (w == 0) {
        int s = wsum[lane];
#pragma unroll
        for (int o = 1; o < 32; o <<= 1) {
            int u = __shfl_up_sync(0xffffffffu, s, o);
            if (lane >= o) s += u;
        }
        wsum[lane] = s;
    }
    __syncthreads();
    int excl = v - local + (w > 0 ? wsum[w - 1] : 0);
    int run = excl;
    for (int i = start; i < end; i++) { g_off[i] = run; run += g_deg[i]; }
}
__global__ void k_scatter(const int* __restrict__ src, const int* __restrict__ dst,
                          const int* __restrict__ et, int E) {
    int e = blockIdx.x * blockDim.x + threadIdx.x;
    if (e >= E) return;
    int d = dst[e];
    int pos = g_off[d] + atomicAdd(&g_cur[d], 1);
    g_epk[pos]  = ((u32)et[e] << 16) | (u32)src[e];
    g_eorig[pos] = e;
}

// ---------------- fused aggregation: warp per destination node ----------------
// mode 0: write bf16 splits to g_xhi/g_xlo (layer-1)
// mode 1: write f32 to out + store g_e/g_s (layer-2)
__global__ void k_agg(float* __restrict__ out, const float* __restrict__ bias,
                      int N, int R, int mode) {
    int d = (blockIdx.x * blockDim.x + threadIdx.x) >> 5;
    int lane = threadIdx.x & 31;
    if (d >= N) return;
    int beg = g_off[d];
    int deg = g_deg[d];
    const float* qrow = g_qi + d * R;

    float acc0 = 0.f, acc1 = 0.f, s = 0.f;

    for (int base = 0; base < deg; base += 4) {
        u32 vv[4];
        int row[4];
#pragma unroll
        for (int j = 0; j < 4; j++) {
            int idx = beg + min(base + j, deg - 1);
            vv[j] = g_epk[idx];
            row[j] = (int)(vv[j] >> 16) * N + (int)(vv[j] & 0xffffu);
        }
        float ev[4];
#pragma unroll
        for (int j = 0; j < 4; j++) {
            float l = qrow[vv[j] >> 16] + g_kj[row[j]];
            l = (l >= 0.f) ? l : 0.2f * l;
            float e = __expf(l);
            ev[j] = (base + j < deg) ? e : 0.f;
            s += ev[j];
        }
#pragma unroll
        for (int j = 0; j < 4; j++) {
            const __half2* xr = (const __half2*)(g_xw16 + (size_t)row[j] * DIM);
            float2 xv = __half22float2(xr[lane]);
            acc0 += ev[j] * xv.x;
            acc1 += ev[j] * xv.y;
        }
        if (mode == 1 && lane == 0) {
#pragma unroll
            for (int j = 0; j < 4; j++)
                if (base + j < deg) g_e[g_eorig[beg + base + j]] = ev[j];
        }
    }

    float inv = 1.f / (s + 1e-16f);
    int c = lane * 2;
    float o0 = fmaxf(acc0 * inv + bias[c],     0.f);
    float o1 = fmaxf(acc1 * inv + bias[c + 1], 0.f);
    if (mode == 0) {
        u32 lo;
        u32 hi = bsplit(o0, o1, lo);
        *(u32*)&g_xhi[(size_t)d * DIM + c] = hi;
        *(u32*)&g_xlo[(size_t)d * DIM + c] = lo;
    } else {
        if (lane == 0) g_s[d] = s;
        *(float2*)&out[(size_t)d * DIM + c] = make_float2(o0, o1);
    }
}

// ---------------- outputs: edge_index copy + alpha ----------------
__global__ void k_out(const int* __restrict__ ei, float* __restrict__ eidxo,
                      float* __restrict__ alpo, const int* __restrict__ dst, int E) {
    int i = blockIdx.x * blockDim.x + threadIdx.x;
    if (i < 2 * E) {
        eidxo[i] = (float)ei[i];
    } else if (i < 3 * E) {
        int e = i - 2 * E;
        alpo[e] = g_e[e] / (g_s[dst[e]] + 1e-16f);
    }
}

// ---------------- host orchestration ----------------
extern "C" void kernel_launch(void* const* d_in, const int* in_sizes, int n_in,
                              void* d_out, int out_size) {
    const float* x   = (const float*)d_in[0];
    const int*   ei  = (const int*)d_in[1];
    const int*   et  = (const int*)d_in[2];
    const float* W1  = (const float*)d_in[3];
    const float* q1  = (const float*)d_in[4];
    const float* k1  = (const float*)d_in[5];
    const float* b1  = (const float*)d_in[6];
    const float* W2  = (const float*)d_in[7];
    const float* q2  = (const float*)d_in[8];
    const float* k2  = (const float*)d_in[9];
    const float* b2  = (const float*)d_in[10];

    const int N = in_sizes[0] / DIM;
    const int E = in_sizes[2];
    const int R = in_sizes[3] / (DIM * DIM);

    const int* src = ei;
    const int* dst = ei + E;

    cudaFuncSetAttribute(k_gemm_mma, cudaFuncAttributeMaxDynamicSharedMemorySize, SM_TOT);

    float* outf  = (float*)d_out;
    float* h2    = outf;
    float* eidxo = outf + (size_t)N * DIM;
    float* alpo  = eidxo + 2 * (size_t)E;

    const dim3 gemmGrid((N + TILE_M - 1) / TILE_M, R / 2);
    const int aggBlocks = (N + 7) / 8;
    const int nx = N * DIM, nw = R * DIM * DIM;

    // idx 0..2
    k_zero<<<(N + 255) / 256, 256>>>(N);
    k_hist<<<(E + 255) / 256, 256>>>(dst, E);
    k_prep<<<(nx + nw + 255) / 256, 256>>>(x, W1, nx, nw, R);
    // idx 3: layer-1 tensor GEMM (ncu profiled slot)
    k_gemm_mma<<<gemmGrid, 256, SM_TOT>>>(q1, k1, N, R);
    // idx 4..5: CSR
    k_scan   <<<1, 1024>>>(N);
    k_scatter<<<(E + 255) / 256, 256>>>(src, dst, et, E);
    // idx 6: layer-1 aggregation (emits bf16 splits directly)
    k_agg<<<aggBlocks, 256>>>(nullptr, b1, N, R, 0);
    // layer 2
    k_splitW<<<(nw + 255) / 256, 256>>>(W2, R);
    k_gemm_mma<<<gemmGrid, 256, SM_TOT>>>(q2, k2, N, R);
    k_agg<<<aggBlocks, 256>>>(h2, b2, N, R, 1);
    // outputs
    k_out<<<(3 * E + 255) / 256, 256>>>(ei, eidxo, alpo, dst, E);
}